// round 3
// baseline (speedup 1.0000x reference)
#include <cuda_runtime.h>
#include <cuda_fp16.h>
#include <stdint.h>

// MX fp8 (e4m3) fake quantization, block=32, shared e8m0 exponent.
//
// Warp layout: each warp owns 512 consecutive floats (128 float4, 16 blocks).
// Each lane does 4 coalesced float4 loads (j*32 + lane); load j of 8-lane
// group g covers quant block 4j+g. Block amax matters only via its fp32
// exponent field (exp-field max == exp field of amax for nonneg floats), so
// the 4 per-load exponent bytes are packed into one u32 and all 4 blocks are
// reduced at once with 3x shfl.bfly + __vmaxu4.
//
// Element quantization uses the HW e4m3 converter:
//   cvt.rn.satfinite.e4m3x2.f32  == round-half-even onto the e4m3 grid
//                                   (subnormal step 2^-9, clamp to +-448)
// which is bit-identical to the reference's priv_exp/pscale/round/clip chain.
// Decode is exact via cvt.rn.f16x2.e4m3x2 + f16->f32.

static __device__ __forceinline__ float2 qdq_pair(float x, float y,
                                                  float inv, float scale) {
    float xs = x * inv;                       // exact (power-of-2 scale)
    float ys = y * inv;
    unsigned short p8;
    // d = { cvt(a) in hi byte, cvt(b) in lo byte } -> keep x in lo
    asm("cvt.rn.satfinite.e4m3x2.f32 %0, %1, %2;"
        : "=h"(p8) : "f"(ys), "f"(xs));
    unsigned h2;
    asm("cvt.rn.f16x2.e4m3x2 %0, %1;" : "=r"(h2) : "h"(p8));
    __half2 hh = *reinterpret_cast<__half2*>(&h2);   // lo=x, hi=y (exact)
    float2 f = __half22float2(hh);
    f.x *= scale;
    f.y *= scale;
    return f;
}

__global__ void __launch_bounds__(256) mx_fp8_fq_kernel(
    const float4* __restrict__ in, float4* __restrict__ out, int n4) {
    int warp = (blockIdx.x * blockDim.x + threadIdx.x) >> 5;
    int lane = threadIdx.x & 31;
    int idx0 = warp * 128 + lane;
    if (idx0 >= n4) return;              // exact-fit grid; cheap guard

    // Front-batched loads: 4 LDG.128 in flight per thread.
    float4 v0 = __ldcs(&in[idx0]);
    float4 v1 = __ldcs(&in[idx0 + 32]);
    float4 v2 = __ldcs(&in[idx0 + 64]);
    float4 v3 = __ldcs(&in[idx0 + 96]);

    // Per-load amax -> exponent byte, 4 blocks packed in one u32.
    float a0 = fmaxf(fmaxf(fabsf(v0.x), fabsf(v0.y)), fmaxf(fabsf(v0.z), fabsf(v0.w)));
    float a1 = fmaxf(fmaxf(fabsf(v1.x), fabsf(v1.y)), fmaxf(fabsf(v1.z), fabsf(v1.w)));
    float a2 = fmaxf(fmaxf(fabsf(v2.x), fabsf(v2.y)), fmaxf(fabsf(v2.z), fabsf(v2.w)));
    float a3 = fmaxf(fmaxf(fabsf(v3.x), fabsf(v3.y)), fmaxf(fabsf(v3.z), fabsf(v3.w)));
    unsigned packed = (__float_as_uint(a0) >> 23)
                    | ((__float_as_uint(a1) >> 23) << 8)
                    | ((__float_as_uint(a2) >> 23) << 16)
                    | ((__float_as_uint(a3) >> 23) << 24);

    // Segmented (8-lane) reduction of all 4 block exponents at once.
    packed = __vmaxu4(packed, __shfl_xor_sync(0xffffffffu, packed, 1));
    packed = __vmaxu4(packed, __shfl_xor_sync(0xffffffffu, packed, 2));
    packed = __vmaxu4(packed, __shfl_xor_sync(0xffffffffu, packed, 4));

    float4 va[4] = {v0, v1, v2, v3};
#pragma unroll
    for (int j = 0; j < 4; j++) {
        int e = (packed >> (8 * j)) & 0xff;
        int sexp = max(e - 135, -127);   // floor(log2(amax)) - 8, clipped low
        // scale = 2^sexp (sexp==-127 -> subnormal 0x00400000); inv = 2^-sexp.
        float scale = __int_as_float(max((sexp + 127) << 23, 0x00400000));
        float inv   = __int_as_float((127 - sexp) << 23);
        float2 lo = qdq_pair(va[j].x, va[j].y, inv, scale);
        float2 hi = qdq_pair(va[j].z, va[j].w, inv, scale);
        float4 r = make_float4(lo.x, lo.y, hi.x, hi.y);
        __stcs(&out[idx0 + 32 * j], r);
    }
}

extern "C" void kernel_launch(void* const* d_in, const int* in_sizes, int n_in,
                              void* d_out, int out_size) {
    const float4* in = (const float4*)d_in[0];
    float4* out = (float4*)d_out;
    int n = in_sizes[0];              // 8192*8192
    int n4 = n / 4;                   // 16,777,216 float4
    int warps = n4 / 128;             // 128 float4 per warp
    int blocks = warps / 8;           // 8 warps per block (256 threads)
    mx_fp8_fq_kernel<<<blocks, 256>>>(in, out, n4);
}